// round 7
// baseline (speedup 1.0000x reference)
#include <cuda_runtime.h>
#include <cuda_fp16.h>
#include <cstdint>

// ======================= problem constants =======================
// B=128, T=1024, M=512 (GEMM N), P=256, K=512, rows = B*T = 131072
static constexpr int NB      = 128;
static constexpr int TLEN    = 1024;
static constexpr int MDIM    = 512;    // N of GEMM
static constexpr int KDIM    = 512;    // inner dim
static constexpr int MTILE   = 64;     // rows per CTA (2 CTAs/SM)
static constexpr int NCHUNK  = 256;    // N per chunk (acc-resident)
static constexpr int NCHUNKS = MDIM / NCHUNK;    // 2
static constexpr int KSEG    = 32;     // K per B buffer / A conversion slice
static constexpr int KSEGS   = KDIM / KSEG;      // 16
static constexpr int NITER   = NCHUNKS * KSEGS;  // 32

// tile-major smem: 8x8 ldsm tile = 128B contiguous; 16x16 tile = 4 subtiles = 512B.
// ldsm address = tile_base + lane*16  -> conflict-free, zero padding.
static constexpr int SMEM_A_BYTES    = MTILE * KDIM * 2;     // 65536
static constexpr int SMEM_BBUF_BYTES = NCHUNK * KSEG * 2;    // 16384
static constexpr int DYN_SMEM = SMEM_A_BYTES + 2 * SMEM_BBUF_BYTES;  // 98304

// ======================= scratch (device globals; no allocs) =======================
__device__ float g_Qt[KDIM * NB];                    // Q transposed [c][b]
__device__ float g_wq[NB * MDIM];                    // wq[b][n]
__device__ __align__(16) __half g_U16[MDIM * KDIM];  // U_d as fp16, [n][k]

// ======================= helpers =======================
__device__ __forceinline__ uint32_t smem_u32(const void* p) {
    return (uint32_t)__cvta_generic_to_shared(p);
}
__device__ __forceinline__ uint32_t pack_h2(float a, float b) {
    __half2 h = __floats2half2_rn(a, b);
    return *reinterpret_cast<uint32_t*>(&h);
}
__device__ __forceinline__ void ldsm_x4(uint32_t addr, uint32_t& r0, uint32_t& r1,
                                        uint32_t& r2, uint32_t& r3) {
    asm volatile("ldmatrix.sync.aligned.m8n8.x4.shared.b16 {%0,%1,%2,%3}, [%4];"
                 : "=r"(r0), "=r"(r1), "=r"(r2), "=r"(r3) : "r"(addr));
}
__device__ __forceinline__ void mma16816(float* c,
                                         const uint32_t* a,
                                         uint32_t b0, uint32_t b1) {
    asm volatile(
        "mma.sync.aligned.m16n8k16.row.col.f32.f16.f16.f32 "
        "{%0,%1,%2,%3}, {%4,%5,%6,%7}, {%8,%9}, {%0,%1,%2,%3};"
        : "+f"(c[0]), "+f"(c[1]), "+f"(c[2]), "+f"(c[3])
        : "r"(a[0]), "r"(a[1]), "r"(a[2]), "r"(a[3]), "r"(b0), "r"(b1));
}
__device__ __forceinline__ void cp_async16(uint32_t dst, const void* src) {
    asm volatile("cp.async.cg.shared.global [%0], [%1], 16;" :: "r"(dst), "l"(src));
}
__device__ __forceinline__ void cp_commit() {
    asm volatile("cp.async.commit_group;" ::: "memory");
}
__device__ __forceinline__ void cp_wait1() {
    asm volatile("cp.async.wait_group 1;" ::: "memory");
}
__device__ __forceinline__ void cp_wait0() {
    asm volatile("cp.async.wait_group 0;" ::: "memory");
}
// tanh(x) = 1 - 2/(e^{2x}+1): 2 MUFU + few ALU, rel err ~1e-6
__device__ __forceinline__ float fast_tanh(float x) {
    float e = __expf(x + x);
    return 1.0f - __fdividef(2.0f, e + 1.0f);
}

// ======================= kernel 1: pack Qt + U -> fp16 =======================
__global__ void __launch_bounds__(256, 1) pack_kernel(const float* __restrict__ dt,
                                                      const float* __restrict__ st,
                                                      const float* __restrict__ Ud) {
    int tid = blockIdx.x * blockDim.x + threadIdx.x;
    int stride = gridDim.x * blockDim.x;
    for (int i = tid; i < KDIM * NB; i += stride) {
        int c = i >> 7, b = i & (NB - 1);
        float v = (c < 256) ? dt[b * 256 + c] : st[b * 256 + (c - 256)];
        g_Qt[c * NB + b] = v;
    }
    for (int i = tid; i < MDIM * KDIM; i += stride)
        g_U16[i] = __float2half_rn(Ud[i]);
}

// ======================= kernel 2: wq[b][n] = sum_c q[b][c]*W_d[n][c] =======================
__global__ void __launch_bounds__(128, 1) wq_kernel(const float* __restrict__ Wd) {
    __shared__ float Ws[8 * KDIM];
    int nbase = blockIdx.x * 8;
    for (int i = threadIdx.x; i < 8 * KDIM; i += 128)
        Ws[i] = Wd[nbase * KDIM + i];
    __syncthreads();
    int b = threadIdx.x;
    float acc[8];
#pragma unroll
    for (int j = 0; j < 8; j++) acc[j] = 0.0f;
    for (int c = 0; c < KDIM; c++) {
        float qv = g_Qt[c * NB + b];
#pragma unroll
        for (int j = 0; j < 8; j++) acc[j] = fmaf(qv, Ws[j * KDIM + c], acc[j]);
    }
#pragma unroll
    for (int j = 0; j < 8; j++) g_wq[b * MDIM + nbase + j] = acc[j];
}

// ======================= dummy kernel: ncu slot steering =======================
__global__ void dummy_kernel() {}

// ======================= kernel 3: fused GEMM(HMMA) + tanh + v-dot =======================
// grid = 2048 CTAs (64 rows each), 512 threads (16 warps), 2 CTAs/SM.
// warp w: rowgrp = w&1 (32 rows each), ngrp = w>>1 (32 n within a 256-n chunk)
__global__ void __launch_bounds__(512, 2) attn_gemm_kernel(const float* __restrict__ H,
                                                           const float* __restrict__ vd,
                                                           float* __restrict__ out) {
    extern __shared__ __align__(16) char dsm[];

    __shared__ float wq_s[MDIM];
    __shared__ float v_s[MDIM];
    __shared__ float score8[8][MTILE];

    const int tid  = threadIdx.x;
    const int wid  = tid >> 5;
    const int lane = tid & 31;
    const int blk  = blockIdx.x;
    const int batch = blk >> 4;               // 16 CTAs of 64 rows per batch (1024 rows)
    const size_t r0 = (size_t)blk * MTILE;

    for (int i = tid; i < MDIM; i += 512) {
        wq_s[i] = g_wq[batch * MDIM + i];
        v_s[i]  = vd[i];
    }

    const uint32_t abase = smem_u32(dsm);
    const uint32_t bbuf0 = abase + SMEM_A_BYTES;

    // ---- B cp.async mapping: 1024 x 16B per buffer, tile-major ----
    // idx -> n = idx>>2, k8 = idx&3 (within 32-k seg)
    // dst = ((n>>4)*2 + (k8>>1))*512 + (((n>>3)&1)*2 + (k8&1))*128 + (n&7)*16
    // ---- issue B iter 0 (chunk 0, kseg 0) ----
    {
#pragma unroll
        for (int it = 0; it < 2; it++) {
            int idx = tid + it * 512;
            int n = idx >> 2, k8 = idx & 3;
            uint32_t doff = (uint32_t)(((n >> 4) * 2 + (k8 >> 1)) * 512 +
                                       (((n >> 3) & 1) * 2 + (k8 & 1)) * 128 + (n & 7) * 16);
            cp_async16(bbuf0 + doff, (const char*)g_U16 + n * 1024 + k8 * 16);
        }
        cp_commit();
    }

    // ---- A conversion: 16 slices of 32 k, 1 float4 per thread per slice ----
    // thread: row = tid>>3, sub8 = tid&7 -> 4 fp32 at k = slice*32 + sub8*4
    const int arow = tid >> 3;
    const int sub8 = tid & 7;
    const float* aSrc = H + (r0 + (size_t)arow) * KDIM + sub8 * 4;
    // dst byte offset (tile-major) for a given slice:
    //   k8 = slice*4 + (sub8>>1); kt = k8>>1; st = ((k8&1)<<1) | ((arow>>3)&1)
    //   off = ((arow>>4)*32 + kt)*512 + st*128 + (arow&7)*16 + (sub8&1)*8
    const int aoff_row = ((arow >> 4) * 32) * 512 + (arow & 7) * 16 + (sub8 & 1) * 8;
    const int arow8 = (arow >> 3) & 1;

    float4 rA;
    {
        rA = *reinterpret_cast<const float4*>(aSrc);
        int k8 = sub8 >> 1;
        uint32_t off = (uint32_t)(aoff_row + (k8 >> 1) * 512 + (((k8 & 1) << 1) | arow8) * 128);
        uint2 u;
        u.x = pack_h2(rA.x, rA.y); u.y = pack_h2(rA.z, rA.w);
        asm volatile("st.shared.v2.b32 [%0], {%1,%2};" :: "r"(abase + off), "r"(u.x), "r"(u.y));
        rA = *reinterpret_cast<const float4*>(aSrc + KSEG);   // slice 1 into regs
    }

    // ---- per-warp tiling ----
    const int rowgrp = wid & 1;     // 2 rowgrps x 32 rows
    const int ngrp   = wid >> 1;    // 8 ngrps x 32 n
    const int rbase  = rowgrp * 32;
    const int rt0    = rowgrp * 2;  // row tiles (16 rows each)
    const int nt0    = ngrp * 2;    // n tiles (16 n each)

    const uint32_t aLane = abase + (uint32_t)(lane * 16);
    const uint32_t bLane0 = bbuf0 + (uint32_t)(lane * 16);

    const int qn = (lane & 3) * 2;
    float s[2][2] = {{0.0f, 0.0f}, {0.0f, 0.0f}};   // [rt][row-half]
    float acc[2][2][2][4];                           // [rt][nt][n8-half][4]

    for (int i = 0; i < NITER; i++) {
        const int kseg  = i & 15;
        const int chunk = i >> 4;
        if (kseg == 0) {
#pragma unroll
            for (int a1 = 0; a1 < 2; a1++)
#pragma unroll
                for (int a2 = 0; a2 < 2; a2++)
#pragma unroll
                    for (int a3 = 0; a3 < 2; a3++)
#pragma unroll
                        for (int q = 0; q < 4; q++) acc[a1][a2][a3][q] = 0.0f;
        }

        __syncthreads();   // buf[(i+1)&1] free; A slice i+1 region not yet read
        if (i + 1 < NITER) {
            const int j = i + 1;
            const int nb_g = (j >> 4) * NCHUNK;
            const int ksb  = (j & 15) * 64;           // byte offset of k seg in g_U16 row
            const uint32_t dst = bbuf0 + (uint32_t)((j & 1) * SMEM_BBUF_BYTES);
#pragma unroll
            for (int it = 0; it < 2; it++) {
                int idx = tid + it * 512;
                int n = idx >> 2, k8 = idx & 3;
                uint32_t doff = (uint32_t)(((n >> 4) * 2 + (k8 >> 1)) * 512 +
                                           (((n >> 3) & 1) * 2 + (k8 & 1)) * 128 + (n & 7) * 16);
                cp_async16(dst + doff,
                           (const char*)g_U16 + (size_t)(nb_g + n) * 1024 + ksb + k8 * 16);
            }
            cp_commit();
        }

        // ---- A pipeline during chunk 0: store slice i+1, load slice i+2 ----
        if (i < 15) {
            int k8 = (i + 1) * 4 + (sub8 >> 1);
            uint32_t off = (uint32_t)(aoff_row + (k8 >> 1) * 512 + (((k8 & 1) << 1) | arow8) * 128);
            uint2 u;
            u.x = pack_h2(rA.x, rA.y); u.y = pack_h2(rA.z, rA.w);
            asm volatile("st.shared.v2.b32 [%0], {%1,%2};" :: "r"(abase + off), "r"(u.x), "r"(u.y));
            if (i + 2 < 16)
                rA = *reinterpret_cast<const float4*>(aSrc + (i + 2) * KSEG);
        }

        if (i + 1 < NITER) cp_wait1(); else cp_wait0();
        __syncthreads();   // buffer i + A slice i visible

        const uint32_t bL = bLane0 + (uint32_t)((i & 1) * SMEM_BBUF_BYTES);

#pragma unroll
        for (int ksi = 0; ksi < 2; ksi++) {
            const int kt = kseg * 2 + ksi;
            uint32_t af[2][4];
            ldsm_x4(aLane + (uint32_t)((rt0 * 32 + kt) * 512),
                    af[0][0], af[0][1], af[0][2], af[0][3]);
            ldsm_x4(aLane + (uint32_t)(((rt0 + 1) * 32 + kt) * 512),
                    af[1][0], af[1][1], af[1][2], af[1][3]);
            uint32_t bf[2][4];
            ldsm_x4(bL + (uint32_t)((nt0 * 2 + ksi) * 512),
                    bf[0][0], bf[0][1], bf[0][2], bf[0][3]);
            ldsm_x4(bL + (uint32_t)(((nt0 + 1) * 2 + ksi) * 512),
                    bf[1][0], bf[1][1], bf[1][2], bf[1][3]);
#pragma unroll
            for (int rt = 0; rt < 2; rt++)
#pragma unroll
                for (int nt = 0; nt < 2; nt++) {
                    mma16816(acc[rt][nt][0], af[rt], bf[nt][0], bf[nt][1]);
                    mma16816(acc[rt][nt][1], af[rt], bf[nt][2], bf[nt][3]);
                }
        }

        if (kseg == 15) {
            // ---- fused epilogue for this 256-n chunk ----
            const int nbase = chunk * NCHUNK + ngrp * 32;
#pragma unroll
            for (int rt = 0; rt < 2; rt++)
#pragma unroll
                for (int nt = 0; nt < 2; nt++)
#pragma unroll
                    for (int h = 0; h < 2; h++) {
                        int n = nbase + nt * 16 + h * 8 + qn;
                        float w0 = wq_s[n], w1 = wq_s[n + 1];
                        float v0 = v_s[n],  v1 = v_s[n + 1];
                        s[rt][0] = fmaf(v0, fast_tanh(w0 + acc[rt][nt][h][0]), s[rt][0]);
                        s[rt][0] = fmaf(v1, fast_tanh(w1 + acc[rt][nt][h][1]), s[rt][0]);
                        s[rt][1] = fmaf(v0, fast_tanh(w0 + acc[rt][nt][h][2]), s[rt][1]);
                        s[rt][1] = fmaf(v1, fast_tanh(w1 + acc[rt][nt][h][3]), s[rt][1]);
                    }
        }
    }

    // ---- final reduction: quad shuffle + per-ngrp arrays ----
#pragma unroll
    for (int rt = 0; rt < 2; rt++)
#pragma unroll
        for (int h = 0; h < 2; h++) {
            s[rt][h] += __shfl_xor_sync(0xffffffffu, s[rt][h], 1);
            s[rt][h] += __shfl_xor_sync(0xffffffffu, s[rt][h], 2);
        }
    if ((lane & 3) == 0) {
        const int rr = lane >> 2;
#pragma unroll
        for (int rt = 0; rt < 2; rt++) {
            score8[ngrp][rbase + rt * 16 + rr]     = s[rt][0];
            score8[ngrp][rbase + rt * 16 + rr + 8] = s[rt][1];
        }
    }
    __syncthreads();
    if (tid < MTILE) {
        float t = 0.0f;
#pragma unroll
        for (int g = 0; g < 8; g++) t += score8[g][tid];
        out[r0 + tid] = t;
    }
}

// ======================= kernel 4: softmax over T, in-place =======================
__global__ void __launch_bounds__(256, 1) softmax_kernel(float* __restrict__ out) {
    __shared__ float red[256];
    float* p = out + (size_t)blockIdx.x * TLEN;
    int tid = threadIdx.x;
    float v[4];
    float m = -1e30f;
#pragma unroll
    for (int j = 0; j < 4; j++) { v[j] = p[tid + j * 256]; m = fmaxf(m, v[j]); }
    red[tid] = m; __syncthreads();
    for (int s = 128; s > 0; s >>= 1) {
        if (tid < s) red[tid] = fmaxf(red[tid], red[tid + s]);
        __syncthreads();
    }
    float mx = red[0];
    __syncthreads();
    float sum = 0.0f;
#pragma unroll
    for (int j = 0; j < 4; j++) { v[j] = __expf(v[j] - mx); sum += v[j]; }
    red[tid] = sum; __syncthreads();
    for (int s = 128; s > 0; s >>= 1) {
        if (tid < s) red[tid] += red[tid + s];
        __syncthreads();
    }
    float inv = 1.0f / red[0];
#pragma unroll
    for (int j = 0; j < 4; j++) p[tid + j * 256] = v[j] * inv;
}

// ======================= launch =======================
extern "C" void kernel_launch(void* const* d_in, const int* in_sizes, int n_in,
                              void* d_out, int out_size) {
    const float *dt = nullptr, *st = nullptr, *H = nullptr;
    const float *W = nullptr, *U = nullptr, *v = nullptr;
    int c32768 = 0, c262144 = 0;
    for (int i = 0; i < n_in; i++) {
        int s = in_sizes[i];
        if (s == 32768)          { if (c32768++ == 0) dt = (const float*)d_in[i]; else st = (const float*)d_in[i]; }
        else if (s == 67108864)  { H = (const float*)d_in[i]; }
        else if (s == 262144)    { if (c262144++ == 0) W = (const float*)d_in[i]; else U = (const float*)d_in[i]; }
        else if (s == 512)       { v = (const float*)d_in[i]; }
    }
    float* out = (float*)d_out;

    cudaFuncSetAttribute(attn_gemm_kernel, cudaFuncAttributeMaxDynamicSharedMemorySize, DYN_SMEM);

    pack_kernel<<<256, 256>>>(dt, st, U);
    wq_kernel<<<64, 128>>>(W);
    dummy_kernel<<<1, 32>>>();   // steer ncu -s 5 slot onto attn_gemm_kernel
    attn_gemm_kernel<<<2048, 512, DYN_SMEM>>>(H, v, out);
    softmax_kernel<<<128, 256>>>(out);
}

// round 8
// speedup vs baseline: 1.0555x; 1.0555x over previous
#include <cuda_runtime.h>
#include <cuda_fp16.h>
#include <cstdint>

// ======================= problem constants =======================
// B=128, T=1024, M=512 (GEMM N), P=256, K=512, rows = B*T = 131072
static constexpr int NB      = 128;
static constexpr int TLEN    = 1024;
static constexpr int NROWS   = 131072;
static constexpr int MDIM    = 512;    // N of GEMM
static constexpr int KDIM    = 512;    // inner dim
static constexpr int MTILE   = 128;    // rows per CTA
static constexpr int NCHUNK  = 256;    // N per chunk (acc-resident)
static constexpr int NCHUNKS = MDIM / NCHUNK;    // 2
static constexpr int KSEG    = 64;     // K per B buffer
static constexpr int KSEGS   = KDIM / KSEG;      // 8
static constexpr int NITER   = NCHUNKS * KSEGS;  // 16

// tile-major smem, 16x16 fp16 tiles of 512B; 16B units XOR-swizzled:
//   A: swA(g) = g ^ ((((g>>5)&3)<<1) | ((g>>4)&1))
//   B: swB(g) = g ^ ((((g>>5)&3)<<1) | ((g>>3)&1))
static constexpr int SMEM_A_BYTES    = MTILE * KDIM * 2;     // 131072
static constexpr int SMEM_BBUF_BYTES = NCHUNK * KSEG * 2;    // 32768
static constexpr int DYN_SMEM = SMEM_A_BYTES + 2 * SMEM_BBUF_BYTES;  // 196608

// ======================= scratch (device globals; no allocs) =======================
__device__ float g_Qt[KDIM * NB];                     // Q transposed [c][b]
__device__ float g_wq[NB * MDIM];                     // wq[b][n]
__device__ __align__(16) __half g_U16[MDIM * KDIM];   // U_d fp16 [n][k]
__device__ __align__(16) __half g_H16[NROWS * KDIM];  // H fp16 [row][k]  (128MB)

// ======================= helpers =======================
__device__ __forceinline__ uint32_t smem_u32(const void* p) {
    return (uint32_t)__cvta_generic_to_shared(p);
}
__device__ __forceinline__ uint32_t pack_h2(float a, float b) {
    __half2 h = __floats2half2_rn(a, b);
    return *reinterpret_cast<uint32_t*>(&h);
}
__device__ __forceinline__ void ldsm_x4(uint32_t addr, uint32_t& r0, uint32_t& r1,
                                        uint32_t& r2, uint32_t& r3) {
    asm volatile("ldmatrix.sync.aligned.m8n8.x4.shared.b16 {%0,%1,%2,%3}, [%4];"
                 : "=r"(r0), "=r"(r1), "=r"(r2), "=r"(r3) : "r"(addr));
}
__device__ __forceinline__ void mma16816(float* c, const uint32_t* a,
                                         uint32_t b0, uint32_t b1) {
    asm volatile(
        "mma.sync.aligned.m16n8k16.row.col.f32.f16.f16.f32 "
        "{%0,%1,%2,%3}, {%4,%5,%6,%7}, {%8,%9}, {%0,%1,%2,%3};"
        : "+f"(c[0]), "+f"(c[1]), "+f"(c[2]), "+f"(c[3])
        : "r"(a[0]), "r"(a[1]), "r"(a[2]), "r"(a[3]), "r"(b0), "r"(b1));
}
__device__ __forceinline__ void cp_async16(uint32_t dst, const void* src) {
    asm volatile("cp.async.cg.shared.global [%0], [%1], 16;" :: "r"(dst), "l"(src));
}
__device__ __forceinline__ void cp_commit() {
    asm volatile("cp.async.commit_group;" ::: "memory");
}
__device__ __forceinline__ void cp_wait1() {
    asm volatile("cp.async.wait_group 1;" ::: "memory");
}
__device__ __forceinline__ void cp_wait0() {
    asm volatile("cp.async.wait_group 0;" ::: "memory");
}
// tanh(x) = 1 - 2/(e^{2x}+1): 2 MUFU, rel err ~1e-6
__device__ __forceinline__ float fast_tanh(float x) {
    float e = __expf(x + x);
    return 1.0f - __fdividef(2.0f, e + 1.0f);
}

// ======================= kernel 0: H fp32 -> fp16 (HBM-bound) =======================
__global__ void __launch_bounds__(256, 1) hconv_kernel(const float* __restrict__ H) {
    const float4* src = reinterpret_cast<const float4*>(H);
    uint32_t i = blockIdx.x * 256 + threadIdx.x;
    uint32_t stride = gridDim.x * 256;
    for (uint32_t j = i; j < (uint32_t)(NROWS / 4) * KDIM; j += stride) {
        float4 f = src[j];
        uint2 u;
        u.x = pack_h2(f.x, f.y);
        u.y = pack_h2(f.z, f.w);
        *reinterpret_cast<uint2*>(g_H16 + (size_t)j * 4) = u;
    }
}

// ======================= kernel 1: pack Qt + U -> fp16 =======================
__global__ void __launch_bounds__(256, 1) pack_kernel(const float* __restrict__ dt,
                                                      const float* __restrict__ st,
                                                      const float* __restrict__ Ud) {
    int tid = blockIdx.x * blockDim.x + threadIdx.x;
    int stride = gridDim.x * blockDim.x;
    for (int i = tid; i < KDIM * NB; i += stride) {
        int c = i >> 7, b = i & (NB - 1);
        float v = (c < 256) ? dt[b * 256 + c] : st[b * 256 + (c - 256)];
        g_Qt[c * NB + b] = v;
    }
    for (int i = tid; i < MDIM * KDIM; i += stride)
        g_U16[i] = __float2half_rn(Ud[i]);
}

// ======================= kernel 2: wq[b][n] = sum_c q[b][c]*W_d[n][c] =======================
__global__ void __launch_bounds__(128, 1) wq_kernel(const float* __restrict__ Wd) {
    __shared__ float Ws[8 * KDIM];
    int nbase = blockIdx.x * 8;
    for (int i = threadIdx.x; i < 8 * KDIM; i += 128)
        Ws[i] = Wd[nbase * KDIM + i];
    __syncthreads();
    int b = threadIdx.x;
    float acc[8];
#pragma unroll
    for (int j = 0; j < 8; j++) acc[j] = 0.0f;
    for (int c = 0; c < KDIM; c++) {
        float qv = g_Qt[c * NB + b];
#pragma unroll
        for (int j = 0; j < 8; j++) acc[j] = fmaf(qv, Ws[j * KDIM + c], acc[j]);
    }
#pragma unroll
    for (int j = 0; j < 8; j++) g_wq[b * MDIM + nbase + j] = acc[j];
}

// ======================= kernel 3: fused GEMM(HMMA) + tanh + v-dot =======================
// grid = 1024 CTAs (128 rows each), 512 threads (16 warps), 1 CTA/SM.
// warp w: rowgrp = w>>2 (32 rows), ngrp = w&3 (64 n within a 256-n chunk)
__global__ void __launch_bounds__(512, 1) attn_gemm_kernel(const float* __restrict__ vd,
                                                           float* __restrict__ out) {
    extern __shared__ __align__(16) char dsm[];

    __shared__ float wq_s[MDIM];
    __shared__ float v_s[MDIM];
    __shared__ float score4[4][MTILE];

    const int tid  = threadIdx.x;
    const int wid  = tid >> 5;
    const int lane = tid & 31;
    const int blk  = blockIdx.x;
    const int batch = blk >> 3;
    const size_t r0 = (size_t)blk * MTILE;

    for (int i = tid; i < MDIM; i += 512) {
        wq_s[i] = g_wq[batch * MDIM + i];
        v_s[i]  = vd[i];
    }

    const uint32_t abase = smem_u32(dsm);
    const uint32_t bbuf0 = abase + SMEM_A_BYTES;

    // ---- B dst/src precompute (iteration-invariant) ----
    uint32_t doffB[4], srcB[4];
#pragma unroll
    for (int it = 0; it < 4; it++) {
        int idx = tid + it * 512;
        int n = idx >> 3, kg = idx & 7;
        int g = ((n >> 4) * 4 + (kg >> 1)) * 32 + (((n >> 3) & 1) * 2 + (kg & 1)) * 8 + (n & 7);
        int gs = g ^ ((((g >> 5) & 3) << 1) | ((g >> 3) & 1));
        doffB[it] = (uint32_t)(gs * 16);
        srcB[it]  = (uint32_t)(n * 1024 + kg * 16);
    }

    // ---- issue B iter 0 (chunk 0, kseg 0) : group 0 ----
#pragma unroll
    for (int it = 0; it < 4; it++)
        cp_async16(bbuf0 + doffB[it], (const char*)g_U16 + srcB[it]);
    cp_commit();

    // ---- issue full A (128 x 512 fp16, swizzled tile-major) : group 1 ----
    {
        const int kgA = tid & 63;
        const int row0 = tid >> 6;               // 0..7
        const int ktA = kgA >> 1, k8A = kgA & 1;
#pragma unroll
        for (int it = 0; it < 16; it++) {
            int row = row0 + it * 8;
            int T = (row >> 4) * 32 + ktA;
            int u = (k8A * 2 + ((row >> 3) & 1)) * 8 + (row & 7);
            int g = T * 32 + u;
            int gs = g ^ ((((g >> 5) & 3) << 1) | ((g >> 4) & 1));
            cp_async16(abase + (uint32_t)(gs * 16),
                       (const char*)g_H16 + (r0 + (size_t)row) * 1024 + kgA * 16);
        }
        cp_commit();
    }

    // ---- per-warp tiling ----
    const int rowgrp = wid >> 2;    // 4 rowgrps x 32 rows
    const int ngrp   = wid & 3;     // 4 ngrps x 64 n
    const int rbase  = rowgrp * 32;
    const int rt0    = rowgrp * 2;  // A 16-row tile base
    const int nt0    = ngrp * 4;    // B 16-n tile base

    const uint32_t aLane = (uint32_t)(lane * 16);
    const int lkA = (lane >> 4) & 1;
    const int lkB = (lane >> 3) & 1;

    const int qn = (lane & 3) * 2;
    float s[4] = {0.0f, 0.0f, 0.0f, 0.0f};
    float acc[2][8][4];

    for (int i = 0; i < NITER; i++) {
        const int kseg  = i & 7;
        const int chunk = i >> 3;
        if (kseg == 0) {
#pragma unroll
            for (int mt = 0; mt < 2; mt++)
#pragma unroll
                for (int j = 0; j < 8; j++)
#pragma unroll
                    for (int q = 0; q < 4; q++) acc[mt][j][q] = 0.0f;
        }

        __syncthreads();   // all warps done reading buf[(i+1)&1]
        if (i + 1 < NITER) {
            const int j = i + 1;
            const uint32_t srcAdd = (uint32_t)((j >> 3) * (NCHUNK * 1024) + (j & 7) * 128);
            const uint32_t dst = bbuf0 + (uint32_t)((j & 1) * SMEM_BBUF_BYTES);
#pragma unroll
            for (int it = 0; it < 4; it++)
                cp_async16(dst + doffB[it], (const char*)g_U16 + srcB[it] + srcAdd);
            cp_commit();
            cp_wait1();    // buffer i complete (iter 0: also waits A)
        } else {
            cp_wait0();
        }
        __syncthreads();   // buffer i (+A) visible to all

        const uint32_t bBuf = bbuf0 + (uint32_t)((i & 1) * SMEM_BBUF_BYTES);

#pragma unroll
        for (int ks = 0; ks < 4; ks++) {
            const uint32_t axor = (uint32_t)((((ks << 1) | lkA)) << 4);
            const uint32_t bxor = (uint32_t)((((ks << 1) | lkB)) << 4);
            const int ktg = kseg * 4 + ks;
            uint32_t af[2][4];
            ldsm_x4(abase + (uint32_t)(((rt0)     * 32 + ktg) * 512) + (aLane ^ axor),
                    af[0][0], af[0][1], af[0][2], af[0][3]);
            ldsm_x4(abase + (uint32_t)(((rt0 + 1) * 32 + ktg) * 512) + (aLane ^ axor),
                    af[1][0], af[1][1], af[1][2], af[1][3]);
            uint32_t bf[4][4];
#pragma unroll
            for (int nb = 0; nb < 4; nb++)
                ldsm_x4(bBuf + (uint32_t)(((nt0 + nb) * 4 + ks) * 512) + (aLane ^ bxor),
                        bf[nb][0], bf[nb][1], bf[nb][2], bf[nb][3]);
#pragma unroll
            for (int mt = 0; mt < 2; mt++)
#pragma unroll
                for (int nb = 0; nb < 4; nb++) {
                    mma16816(acc[mt][nb * 2],     af[mt], bf[nb][0], bf[nb][1]);
                    mma16816(acc[mt][nb * 2 + 1], af[mt], bf[nb][2], bf[nb][3]);
                }
        }

        if (kseg == 7) {
            // ---- fused epilogue for this 256-n chunk ----
            const int nbase = chunk * NCHUNK + ngrp * 64;
#pragma unroll
            for (int mt = 0; mt < 2; mt++)
#pragma unroll
                for (int j = 0; j < 8; j++) {
                    int n = nbase + (j >> 1) * 16 + (j & 1) * 8 + qn;
                    float w0 = wq_s[n], w1 = wq_s[n + 1];
                    float v0 = v_s[n],  v1 = v_s[n + 1];
                    s[mt * 2]     = fmaf(v0, fast_tanh(w0 + acc[mt][j][0]), s[mt * 2]);
                    s[mt * 2]     = fmaf(v1, fast_tanh(w1 + acc[mt][j][1]), s[mt * 2]);
                    s[mt * 2 + 1] = fmaf(v0, fast_tanh(w0 + acc[mt][j][2]), s[mt * 2 + 1]);
                    s[mt * 2 + 1] = fmaf(v1, fast_tanh(w1 + acc[mt][j][3]), s[mt * 2 + 1]);
                }
        }
    }

    // ---- final reduction: quad shuffle + per-ngrp arrays ----
#pragma unroll
    for (int q = 0; q < 4; q++) {
        s[q] += __shfl_xor_sync(0xffffffffu, s[q], 1);
        s[q] += __shfl_xor_sync(0xffffffffu, s[q], 2);
    }
    if ((lane & 3) == 0) {
        const int rr = rbase + (lane >> 2);
        score4[ngrp][rr]      = s[0];
        score4[ngrp][rr + 8]  = s[1];
        score4[ngrp][rr + 16] = s[2];
        score4[ngrp][rr + 24] = s[3];
    }
    __syncthreads();
    if (tid < MTILE)
        out[r0 + tid] = (score4[0][tid] + score4[1][tid]) + (score4[2][tid] + score4[3][tid]);
}

// ======================= kernel 4: softmax over T, in-place =======================
__global__ void __launch_bounds__(256, 1) softmax_kernel(float* __restrict__ out) {
    __shared__ float red[256];
    float* p = out + (size_t)blockIdx.x * TLEN;
    int tid = threadIdx.x;
    float v[4];
    float m = -1e30f;
#pragma unroll
    for (int j = 0; j < 4; j++) { v[j] = p[tid + j * 256]; m = fmaxf(m, v[j]); }
    red[tid] = m; __syncthreads();
    for (int s = 128; s > 0; s >>= 1) {
        if (tid < s) red[tid] = fmaxf(red[tid], red[tid + s]);
        __syncthreads();
    }
    float mx = red[0];
    __syncthreads();
    float sum = 0.0f;
#pragma unroll
    for (int j = 0; j < 4; j++) { v[j] = __expf(v[j] - mx); sum += v[j]; }
    red[tid] = sum; __syncthreads();
    for (int s = 128; s > 0; s >>= 1) {
        if (tid < s) red[tid] += red[tid + s];
        __syncthreads();
    }
    float inv = 1.0f / red[0];
#pragma unroll
    for (int j = 0; j < 4; j++) p[tid + j * 256] = v[j] * inv;
}

// ======================= launch =======================
extern "C" void kernel_launch(void* const* d_in, const int* in_sizes, int n_in,
                              void* d_out, int out_size) {
    const float *dt = nullptr, *st = nullptr, *H = nullptr;
    const float *W = nullptr, *U = nullptr, *v = nullptr;
    int c32768 = 0, c262144 = 0;
    for (int i = 0; i < n_in; i++) {
        int s = in_sizes[i];
        if (s == 32768)          { if (c32768++ == 0) dt = (const float*)d_in[i]; else st = (const float*)d_in[i]; }
        else if (s == 67108864)  { H = (const float*)d_in[i]; }
        else if (s == 262144)    { if (c262144++ == 0) W = (const float*)d_in[i]; else U = (const float*)d_in[i]; }
        else if (s == 512)       { v = (const float*)d_in[i]; }
    }
    float* out = (float*)d_out;

    cudaFuncSetAttribute(attn_gemm_kernel, cudaFuncAttributeMaxDynamicSharedMemorySize, DYN_SMEM);

    hconv_kernel<<<2048, 256>>>(H);          // abs launch idx 2
    pack_kernel<<<256, 256>>>(dt, st, U);    // 3
    wq_kernel<<<64, 128>>>(W);               // 4
    attn_gemm_kernel<<<1024, 512, DYN_SMEM>>>(v, out);   // 5 <- ncu -s 5 target
    softmax_kernel<<<128, 256>>>(out);
}

// round 9
// speedup vs baseline: 1.5352x; 1.4544x over previous
#include <cuda_runtime.h>
#include <cuda_fp16.h>
#include <cstdint>

// ======================= problem constants =======================
// B=128, T=1024, M=512 (GEMM N), P=256, K=512, rows = B*T = 131072
static constexpr int NB      = 128;
static constexpr int TLEN    = 1024;
static constexpr int MDIM    = 512;    // N of GEMM
static constexpr int KDIM    = 512;    // inner dim
static constexpr int MTILE   = 128;    // rows per CTA
static constexpr int NCHUNK  = 256;    // N per chunk (acc-resident)
static constexpr int NCHUNKS = MDIM / NCHUNK;    // 2
static constexpr int KSEG    = 32;     // K per B buffer / A slice
static constexpr int KSEGS   = KDIM / KSEG;      // 16
static constexpr int NITER   = NCHUNKS * KSEGS;  // 32

// padded strides (halves): rotate bank groups -> conflict-free ldmatrix
static constexpr int APAD  = 520;      // 1040 B/row
static constexpr int BPAD  = 40;       // 80 B/row (32k*2B + 16B pad)

static constexpr int SMEM_A_BYTES    = MTILE * APAD * 2;     // 133120
static constexpr int SMEM_BBUF_BYTES = NCHUNK * BPAD * 2;    // 20480
static constexpr int NBUF = 3;
static constexpr int DYN_SMEM = SMEM_A_BYTES + NBUF * SMEM_BBUF_BYTES;  // 194560

// ======================= scratch (device globals; no allocs) =======================
__device__ float g_Qt[KDIM * NB];                    // Q transposed [c][b]
__device__ float g_wq[NB * MDIM];                    // wq[b][n]
__device__ __align__(16) __half g_U16[MDIM * KDIM];  // U_d fp16 [n][k]

// ======================= helpers =======================
__device__ __forceinline__ uint32_t smem_u32(const void* p) {
    return (uint32_t)__cvta_generic_to_shared(p);
}
__device__ __forceinline__ uint32_t pack_h2(float a, float b) {
    __half2 h = __floats2half2_rn(a, b);
    return *reinterpret_cast<uint32_t*>(&h);
}
__device__ __forceinline__ void ldsm_x4(uint32_t addr, uint32_t& r0, uint32_t& r1,
                                        uint32_t& r2, uint32_t& r3) {
    asm volatile("ldmatrix.sync.aligned.m8n8.x4.shared.b16 {%0,%1,%2,%3}, [%4];"
                 : "=r"(r0), "=r"(r1), "=r"(r2), "=r"(r3) : "r"(addr));
}
__device__ __forceinline__ void mma16816(float* c, const uint32_t* a,
                                         uint32_t b0, uint32_t b1) {
    asm volatile(
        "mma.sync.aligned.m16n8k16.row.col.f32.f16.f16.f32 "
        "{%0,%1,%2,%3}, {%4,%5,%6,%7}, {%8,%9}, {%0,%1,%2,%3};"
        : "+f"(c[0]), "+f"(c[1]), "+f"(c[2]), "+f"(c[3])
        : "r"(a[0]), "r"(a[1]), "r"(a[2]), "r"(a[3]), "r"(b0), "r"(b1));
}
__device__ __forceinline__ void cp_async16(uint32_t dst, const void* src) {
    asm volatile("cp.async.cg.shared.global [%0], [%1], 16;" :: "r"(dst), "l"(src));
}
__device__ __forceinline__ void cp_commit() {
    asm volatile("cp.async.commit_group;" ::: "memory");
}
__device__ __forceinline__ void cp_wait1() {
    asm volatile("cp.async.wait_group 1;" ::: "memory");
}
__device__ __forceinline__ void cp_wait0() {
    asm volatile("cp.async.wait_group 0;" ::: "memory");
}
// tanh(x) = 1 - 2/(e^{2x}+1): 2 MUFU, rel err ~1e-6
__device__ __forceinline__ float fast_tanh(float x) {
    float e = __expf(x + x);
    return 1.0f - __fdividef(2.0f, e + 1.0f);
}

// ======================= kernel 1: pack Qt + U -> fp16 =======================
__global__ void __launch_bounds__(256, 1) pack_kernel(const float* __restrict__ dt,
                                                      const float* __restrict__ st,
                                                      const float* __restrict__ Ud) {
    int tid = blockIdx.x * blockDim.x + threadIdx.x;
    int stride = gridDim.x * blockDim.x;
    for (int i = tid; i < KDIM * NB; i += stride) {
        int c = i >> 7, b = i & (NB - 1);
        float v = (c < 256) ? dt[b * 256 + c] : st[b * 256 + (c - 256)];
        g_Qt[c * NB + b] = v;
    }
    for (int i = tid; i < MDIM * KDIM; i += stride)
        g_U16[i] = __float2half_rn(Ud[i]);
}

// ======================= kernel 2: wq[b][n] = sum_c q[b][c]*W_d[n][c] =======================
__global__ void __launch_bounds__(128, 1) wq_kernel(const float* __restrict__ Wd) {
    __shared__ float Ws[8 * KDIM];
    int nbase = blockIdx.x * 8;
    for (int i = threadIdx.x; i < 8 * KDIM; i += 128)
        Ws[i] = Wd[nbase * KDIM + i];
    __syncthreads();
    int b = threadIdx.x;
    float acc[8];
#pragma unroll
    for (int j = 0; j < 8; j++) acc[j] = 0.0f;
    for (int c = 0; c < KDIM; c++) {
        float qv = g_Qt[c * NB + b];
#pragma unroll
        for (int j = 0; j < 8; j++) acc[j] = fmaf(qv, Ws[j * KDIM + c], acc[j]);
    }
#pragma unroll
    for (int j = 0; j < 8; j++) g_wq[b * MDIM + nbase + j] = acc[j];
}

// ======================= dummy kernel: ncu slot steering =======================
__global__ void dummy_kernel() {}

// ======================= kernel 3: fused GEMM(HMMA) + tanh + v-dot =======================
// grid = 1024 CTAs (128 rows each), 512 threads (16 warps), 1 CTA/SM.
// warp w: rowgrp = w>>2 (32 rows), ngrp = w&3 (64 n within a 256-n chunk)
__global__ void __launch_bounds__(512, 1) attn_gemm_kernel(const float* __restrict__ H,
                                                           const float* __restrict__ vd,
                                                           float* __restrict__ out) {
    extern __shared__ __align__(16) char dsm[];
    __half* smemA = reinterpret_cast<__half*>(dsm);
    char*   smemB = dsm + SMEM_A_BYTES;

    __shared__ float wq_s[MDIM];
    __shared__ float v_s[MDIM];
    __shared__ float score4[4][MTILE];

    const int tid  = threadIdx.x;
    const int wid  = tid >> 5;
    const int lane = tid & 31;
    const int blk  = blockIdx.x;
    const int batch = blk >> 3;
    const size_t r0 = (size_t)blk * MTILE;

    for (int i = tid; i < MDIM; i += 512) {
        wq_s[i] = g_wq[batch * MDIM + i];
        v_s[i]  = vd[i];
    }

    const uint32_t bbuf0 = smem_u32(smemB);

    // ---- B cp.async mapping: 1024 x 16B per buffer; idx -> n = idx>>2, kg = idx&3 ----
    // dst = n*80 + kg*16 ; src(iter j) = g_U16 + ((j>>4)*256 + n)*1024 + (j&15)*64 + kg*16
    const int bn0 = tid >> 1;            // idx = tid*? -> use idx = tid + it*512
    (void)bn0;

    // ---- issue B for iters 0 and 1 (two groups) ----
#pragma unroll
    for (int j = 0; j < 2; j++) {
        const uint32_t dst = bbuf0 + (uint32_t)(j * SMEM_BBUF_BYTES);
#pragma unroll
        for (int it = 0; it < 2; it++) {
            int idx = tid + it * 512;
            int n = idx >> 2, kg = idx & 3;
            cp_async16(dst + (uint32_t)(n * 80 + kg * 16),
                       (const char*)g_U16 + n * 1024 + j * 64 + kg * 16);
        }
        cp_commit();
    }

    // ---- A conversion: 16 slices of 32 k; thread: row = tid>>2, 8 k at (tid&3)*8 ----
    const int arow = tid >> 2;
    const int akq  = (tid & 3) * 8;
    const float* aSrc = H + (r0 + (size_t)arow) * KDIM + akq;
    __half* aDst = smemA + arow * APAD + akq;

    float4 rA0, rA1;
    {   // store slice 0, load slice 1 into regs
        const float4* s0 = reinterpret_cast<const float4*>(aSrc);
        rA0 = s0[0]; rA1 = s0[1];
        uint4 u;
        u.x = pack_h2(rA0.x, rA0.y); u.y = pack_h2(rA0.z, rA0.w);
        u.z = pack_h2(rA1.x, rA1.y); u.w = pack_h2(rA1.z, rA1.w);
        *reinterpret_cast<uint4*>(aDst) = u;
        const float4* s1 = reinterpret_cast<const float4*>(aSrc + KSEG);
        rA0 = s1[0]; rA1 = s1[1];
    }

    // ---- per-lane ldmatrix addressing (R5 layout) ----
    const int sub = lane >> 3;      // 8x8 tile index within x4
    const int l8  = lane & 7;
    const int rowgrp = wid >> 2;    // 4 rowgrps x 32 rows
    const int ngrp   = wid & 3;     // 4 ngrps x 64 n
    const int rbase  = rowgrp * 32;

    // A x4 tiles: t0 r0-7/k0-7, t1 r8-15/k0-7, t2 r0-7/k8-15, t3 r8-15/k8-15
    const uint32_t aAddr0 = smem_u32(smemA) +
        (uint32_t)(((rbase + (sub & 1) * 8 + l8) * APAD + (sub >> 1) * 8) * 2);
    const uint32_t aAddr1 = aAddr0 + (uint32_t)(16 * APAD * 2);
    // B x4 tiles: t0 n0-7/k0-7, t1 n0-7/k8-15, t2 n8-15/k0-7, t3 n8-15/k8-15
    const uint32_t bOff = (uint32_t)((ngrp * 64 + (sub >> 1) * 8 + l8) * 80 + (sub & 1) * 16);

    const int qn = (lane & 3) * 2;
    float s[4] = {0.0f, 0.0f, 0.0f, 0.0f};
    float acc[2][8][4];

    for (int i = 0; i < NITER; i++) {
        const int kseg  = i & 15;
        const int chunk = i >> 4;
        if (kseg == 0) {
#pragma unroll
            for (int mt = 0; mt < 2; mt++)
#pragma unroll
                for (int j = 0; j < 8; j++)
#pragma unroll
                    for (int q = 0; q < 4; q++) acc[mt][j][q] = 0.0f;
        }

        // ---- wait for group i (pending: g_i, g_{i+1}) then ONE barrier ----
        if (i + 1 < NITER) cp_wait1(); else cp_wait0();
        __syncthreads();
        // barrier also proves compute(i-1) done -> buf[(i+2)%3] = buf[(i-1)%3] is free

        if (i + 2 < NITER) {
            const int j = i + 2;
            const int nb_g = (j >> 4) * NCHUNK;
            const int ksb  = (j & 15) * 64;
            const uint32_t dst = bbuf0 + (uint32_t)((j % 3) * SMEM_BBUF_BYTES);
#pragma unroll
            for (int it = 0; it < 2; it++) {
                int idx = tid + it * 512;
                int n = idx >> 2, kg = idx & 3;
                cp_async16(dst + (uint32_t)(n * 80 + kg * 16),
                           (const char*)g_U16 + (size_t)(nb_g + n) * 1024 + ksb + kg * 16);
            }
            cp_commit();
        }

        // ---- A pipeline during chunk 0: store slice i+1, load slice i+2 ----
        if (i < 15) {
            uint4 u;
            u.x = pack_h2(rA0.x, rA0.y); u.y = pack_h2(rA0.z, rA0.w);
            u.z = pack_h2(rA1.x, rA1.y); u.w = pack_h2(rA1.z, rA1.w);
            *reinterpret_cast<uint4*>(aDst + (i + 1) * KSEG) = u;
            if (i + 2 < 16) {
                const float4* sN = reinterpret_cast<const float4*>(aSrc + (i + 2) * KSEG);
                rA0 = sN[0]; rA1 = sN[1];
            }
        }

        // ---- compute iter i: 2 k16-steps ----
        const uint32_t bA = bbuf0 + (uint32_t)((i % 3) * SMEM_BBUF_BYTES) + bOff;
        const uint32_t aK = (uint32_t)(kseg * 64);   // kseg*32k*2B

#pragma unroll
        for (int ks = 0; ks < 2; ks++) {
            uint32_t af[2][4];
            ldsm_x4(aAddr0 + aK + ks * 32, af[0][0], af[0][1], af[0][2], af[0][3]);
            ldsm_x4(aAddr1 + aK + ks * 32, af[1][0], af[1][1], af[1][2], af[1][3]);
            uint32_t bf[4][4];
#pragma unroll
            for (int nb = 0; nb < 4; nb++)
                ldsm_x4(bA + nb * (16 * 80) + ks * 32,
                        bf[nb][0], bf[nb][1], bf[nb][2], bf[nb][3]);
#pragma unroll
            for (int mt = 0; mt < 2; mt++)
#pragma unroll
                for (int nb = 0; nb < 4; nb++) {
                    mma16816(acc[mt][nb * 2],     af[mt], bf[nb][0], bf[nb][1]);
                    mma16816(acc[mt][nb * 2 + 1], af[mt], bf[nb][2], bf[nb][3]);
                }
        }

        if (kseg == 15) {
            // ---- fused epilogue for this 256-n chunk ----
            const int nbase = chunk * NCHUNK + ngrp * 64;
#pragma unroll
            for (int mt = 0; mt < 2; mt++)
#pragma unroll
                for (int j = 0; j < 8; j++) {
                    int n = nbase + (j >> 1) * 16 + (j & 1) * 8 + qn;
                    float w0 = wq_s[n], w1 = wq_s[n + 1];
                    float v0 = v_s[n],  v1 = v_s[n + 1];
                    s[mt * 2]     = fmaf(v0, fast_tanh(w0 + acc[mt][j][0]), s[mt * 2]);
                    s[mt * 2]     = fmaf(v1, fast_tanh(w1 + acc[mt][j][1]), s[mt * 2]);
                    s[mt * 2 + 1] = fmaf(v0, fast_tanh(w0 + acc[mt][j][2]), s[mt * 2 + 1]);
                    s[mt * 2 + 1] = fmaf(v1, fast_tanh(w1 + acc[mt][j][3]), s[mt * 2 + 1]);
                }
        }
    }

    // ---- final reduction: quad shuffle + per-ngrp arrays ----
#pragma unroll
    for (int q = 0; q < 4; q++) {
        s[q] += __shfl_xor_sync(0xffffffffu, s[q], 1);
        s[q] += __shfl_xor_sync(0xffffffffu, s[q], 2);
    }
    if ((lane & 3) == 0) {
        const int rr = rbase + (lane >> 2);
        score4[ngrp][rr]      = s[0];
        score4[ngrp][rr + 8]  = s[1];
        score4[ngrp][rr + 16] = s[2];
        score4[ngrp][rr + 24] = s[3];
    }
    __syncthreads();
    if (tid < MTILE)
        out[r0 + tid] = (score4[0][tid] + score4[1][tid]) + (score4[2][tid] + score4[3][tid]);
}

// ======================= kernel 4: softmax over T, in-place =======================
__global__ void __launch_bounds__(256, 1) softmax_kernel(float* __restrict__ out) {
    __shared__ float red[256];
    float* p = out + (size_t)blockIdx.x * TLEN;
    int tid = threadIdx.x;
    float v[4];
    float m = -1e30f;
#pragma unroll
    for (int j = 0; j < 4; j++) { v[j] = p[tid + j * 256]; m = fmaxf(m, v[j]); }
    red[tid] = m; __syncthreads();
    for (int s = 128; s > 0; s >>= 1) {
        if (tid < s) red[tid] = fmaxf(red[tid], red[tid + s]);
        __syncthreads();
    }
    float mx = red[0];
    __syncthreads();
    float sum = 0.0f;
#pragma unroll
    for (int j = 0; j < 4; j++) { v[j] = __expf(v[j] - mx); sum += v[j]; }
    red[tid] = sum; __syncthreads();
    for (int s = 128; s > 0; s >>= 1) {
        if (tid < s) red[tid] += red[tid + s];
        __syncthreads();
    }
    float inv = 1.0f / red[0];
#pragma unroll
    for (int j = 0; j < 4; j++) p[tid + j * 256] = v[j] * inv;
}

// ======================= launch =======================
extern "C" void kernel_launch(void* const* d_in, const int* in_sizes, int n_in,
                              void* d_out, int out_size) {
    const float *dt = nullptr, *st = nullptr, *H = nullptr;
    const float *W = nullptr, *U = nullptr, *v = nullptr;
    int c32768 = 0, c262144 = 0;
    for (int i = 0; i < n_in; i++) {
        int s = in_sizes[i];
        if (s == 32768)          { if (c32768++ == 0) dt = (const float*)d_in[i]; else st = (const float*)d_in[i]; }
        else if (s == 67108864)  { H = (const float*)d_in[i]; }
        else if (s == 262144)    { if (c262144++ == 0) W = (const float*)d_in[i]; else U = (const float*)d_in[i]; }
        else if (s == 512)       { v = (const float*)d_in[i]; }
    }
    float* out = (float*)d_out;

    cudaFuncSetAttribute(attn_gemm_kernel, cudaFuncAttributeMaxDynamicSharedMemorySize, DYN_SMEM);

    pack_kernel<<<256, 256>>>(dt, st, U);      // abs idx 2
    wq_kernel<<<64, 128>>>(W);                 // 3
    dummy_kernel<<<1, 32>>>();                 // 4
    attn_gemm_kernel<<<1024, 512, DYN_SMEM>>>(H, v, out);   // 5 <- ncu -s 5
    softmax_kernel<<<128, 256>>>(out);
}